// round 2
// baseline (speedup 1.0000x reference)
#include <cuda_runtime.h>
#include <cuda_bf16.h>
#include <cstdint>

// ============================================================
// PrototypeLayer: out[b,p,h,w] = log((d+1)/(d+eps)),
//   d = ||x[b,:,h,w] - proto[p,:]||^2
// GEMM: M=2000 protos (pad 2048), N=64*196=12544 pixels, K=512
// Base-sm_100 ISA only: mma.sync (HMMA) + ldmatrix + cp.async.
// ============================================================

#define EPSV 1e-4f

static constexpr int NPIX   = 12544;      // 64*196
static constexpr int KDIM   = 512;
static constexpr int MT_N   = 16;         // m tiles of 128 -> 2048 padded
static constexpr int NT_N   = 98;         // n tiles of 128 -> 12544 exact
static constexpr int KC_N   = 8;          // k chunks of 64
static constexpr int A_TILE = 128 * 128;  // 128 rows x 64 bf16 (128B rows) = 16KB
static constexpr int B_TILE = 128 * 128;  // 128 pixels x 64 bf16 = 16KB

// scratch (device globals; no allocation allowed)
static __device__ __align__(1024) unsigned char gA[MT_N * KC_N * A_TILE];  // 2 MB
static __device__ __align__(1024) unsigned char gB[NT_N * KC_N * B_TILE];  // 12.8 MB
static __device__ float g_x2p[KC_N * NPIX];
static __device__ float g_x2[NPIX];
static __device__ float g_p2[2048];

// ---------------- helpers ----------------
__device__ __forceinline__ uint32_t swz128(uint32_t b) { return b ^ ((b >> 3) & 0x70); }

__device__ __forceinline__ uint32_t s2u(const void* p) {
    uint32_t a;
    asm("{ .reg .u64 t; cvta.to.shared.u64 t, %1; cvt.u32.u64 %0, t; }" : "=r"(a) : "l"(p));
    return a;
}

__device__ __forceinline__ uint32_t bfpack(float a, float b) {
    __nv_bfloat162 h = __floats2bfloat162_rn(a, b);
    return *reinterpret_cast<uint32_t*>(&h);
}

__device__ __forceinline__ void cp16(uint32_t saddr, const void* gaddr) {
    asm volatile("cp.async.cg.shared.global [%0], [%1], 16;" :: "r"(saddr), "l"(gaddr) : "memory");
}
__device__ __forceinline__ void cp_commit() {
    asm volatile("cp.async.commit_group;" ::: "memory");
}
template <int N>
__device__ __forceinline__ void cp_wait() {
    asm volatile("cp.async.wait_group %0;" :: "n"(N) : "memory");
}

__device__ __forceinline__ void ldsm_x4(uint32_t& r0, uint32_t& r1, uint32_t& r2, uint32_t& r3,
                                        uint32_t addr) {
    asm volatile("ldmatrix.sync.aligned.m8n8.x4.shared.b16 {%0,%1,%2,%3}, [%4];"
                 : "=r"(r0), "=r"(r1), "=r"(r2), "=r"(r3) : "r"(addr));
}

__device__ __forceinline__ void mma16816(float* c, uint32_t a0, uint32_t a1, uint32_t a2,
                                         uint32_t a3, uint32_t b0, uint32_t b1) {
    asm volatile(
        "mma.sync.aligned.m16n8k16.row.col.f32.bf16.bf16.f32 "
        "{%0,%1,%2,%3}, {%4,%5,%6,%7}, {%8,%9}, {%0,%1,%2,%3};"
        : "+f"(c[0]), "+f"(c[1]), "+f"(c[2]), "+f"(c[3])
        : "r"(a0), "r"(a1), "r"(a2), "r"(a3), "r"(b0), "r"(b1));
}

// ---------------- pre-pass: prototypes -> swizzled bf16 tiles ----------------
__global__ void prep_protos(const float* __restrict__ protos) {
    int mt = blockIdx.x, kc = blockIdx.y;
    int t = threadIdx.x;  // 256
    unsigned char* dst = gA + (size_t)(mt * KC_N + kc) * A_TILE;
#pragma unroll
    for (int it = 0; it < 4; it++) {
        int item = t + it * 256;  // 0..1023
        int row = item >> 3;
        int ch = item & 7;
        int p = mt * 128 + row;
        float4 f0, f1;
        if (p < 2000) {
            const float4* src =
                reinterpret_cast<const float4*>(protos + (size_t)p * KDIM + kc * 64 + ch * 8);
            f0 = src[0];
            f1 = src[1];
        } else {
            f0 = make_float4(0.f, 0.f, 0.f, 0.f);
            f1 = f0;
        }
        uint4 o;
        o.x = bfpack(f0.x, f0.y);
        o.y = bfpack(f0.z, f0.w);
        o.z = bfpack(f1.x, f1.y);
        o.w = bfpack(f1.z, f1.w);
        *reinterpret_cast<uint4*>(dst + swz128(row * 128 + ch * 16)) = o;
    }
}

__global__ void prep_p2(const float* __restrict__ protos) {
    int w = threadIdx.x >> 5, lid = threadIdx.x & 31;
    int r = blockIdx.x * 8 + w;  // 0..2047
    float acc = 0.f;
    if (r < 2000) {
        const float* row = protos + (size_t)r * KDIM;
        for (int j = lid; j < KDIM; j += 32) {
            float v = row[j];
            acc = fmaf(v, v, acc);
        }
    }
#pragma unroll
    for (int o = 16; o; o >>= 1) acc += __shfl_xor_sync(0xFFFFFFFFu, acc, o);
    if (lid == 0) g_p2[r] = acc;
}

// x -> transposed swizzled bf16 tiles + partial x2  (grid: (NT_N, KC_N) x 128 thr)
__global__ void prep_x(const float* __restrict__ x) {
    int nt = blockIdx.x, kc = blockIdx.y;
    int t = threadIdx.x;  // 128
    int n = nt * 128 + t;
    int b = n / 196;
    int hw = n - b * 196;
    const float* base = x + (size_t)b * KDIM * 196 + hw;
    unsigned char* dst = gB + (size_t)(nt * KC_N + kc) * B_TILE;
    float acc = 0.f;
#pragma unroll
    for (int ch = 0; ch < 8; ch++) {
        uint32_t u[4];
#pragma unroll
        for (int pair = 0; pair < 4; pair++) {
            int c0 = kc * 64 + ch * 8 + pair * 2;
            float v0 = base[(size_t)c0 * 196];
            float v1 = base[(size_t)(c0 + 1) * 196];
            acc = fmaf(v0, v0, acc);
            acc = fmaf(v1, v1, acc);
            u[pair] = bfpack(v0, v1);
        }
        uint4 o;
        o.x = u[0]; o.y = u[1]; o.z = u[2]; o.w = u[3];
        *reinterpret_cast<uint4*>(dst + swz128(t * 128 + ch * 16)) = o;
    }
    g_x2p[kc * NPIX + n] = acc;
}

__global__ void reduce_x2() {
    int n = blockIdx.x * 256 + threadIdx.x;
    float s = 0.f;
#pragma unroll
    for (int j = 0; j < KC_N; j++) s += g_x2p[j * NPIX + n];
    g_x2[n] = s;
}

// ---------------- main GEMM + fused epilogue ----------------
static constexpr int STAGES = 3;
static constexpr int STAGE_BYTES = A_TILE + B_TILE;         // 32768
static constexpr int OFF_X2S = STAGES * STAGE_BYTES;        // 98304
static constexpr int SMEM_SZ = OFF_X2S + 512;               // 98816

__global__ void __launch_bounds__(256) gemm_kernel(float* __restrict__ out) {
    extern __shared__ __align__(1024) char smem[];
    const uint32_t sb = s2u(smem);
    const int tid = threadIdx.x;
    const int nt = blockIdx.x, mt = blockIdx.y;

    const unsigned char* ga = gA + (size_t)mt * KC_N * A_TILE;
    const unsigned char* gb = gB + (size_t)nt * KC_N * B_TILE;

    // stage loader: pure linear 16B copies (tiles are pre-swizzled smem images)
    auto load_stage = [&](int c) {
        if (c < KC_N) {
            int s = c % STAGES;
            uint32_t sa = sb + s * STAGE_BYTES;
            const unsigned char* pa = ga + (size_t)c * A_TILE;
            const unsigned char* pb = gb + (size_t)c * B_TILE;
#pragma unroll
            for (int i = 0; i < 4; i++) {
                uint32_t off = tid * 16 + i * 4096;
                cp16(sa + off, pa + off);
                cp16(sa + A_TILE + off, pb + off);
            }
        }
        cp_commit();
    };

    if (tid < 128) ((float*)(smem + OFF_X2S))[tid] = g_x2[nt * 128 + tid];

    load_stage(0);
    load_stage(1);

    const int w = tid >> 5, lane = tid & 31;
    const int wm = w & 3;   // 4 M-warps: rows wm*32..+31
    const int wn = w >> 2;  // 2 N-warps: cols wn*64..+63

    float acc[2][8][4];
#pragma unroll
    for (int i = 0; i < 2; i++)
#pragma unroll
        for (int j = 0; j < 8; j++)
#pragma unroll
            for (int q = 0; q < 4; q++) acc[i][j][q] = 0.f;

    const int lrow = lane & 15;   // ldmatrix row within 16
    const int lhalf = lane >> 4;  // ldmatrix 8-col half

    for (int c = 0; c < KC_N; c++) {
        cp_wait<1>();
        __syncthreads();
        load_stage(c + 2);

        const uint32_t sa = sb + (c % STAGES) * STAGE_BYTES;
        const uint32_t sB = sa + A_TILE;
#pragma unroll
        for (int k16 = 0; k16 < 4; k16++) {
            const uint32_t kb = k16 * 32 + lhalf * 16;
            // A frags: 2 x m16
            uint32_t a[2][4];
#pragma unroll
            for (int mi = 0; mi < 2; mi++) {
                int row = wm * 32 + mi * 16 + lrow;
                ldsm_x4(a[mi][0], a[mi][1], a[mi][2], a[mi][3],
                        sa + swz128(row * 128 + kb));
            }
            // B frags: 4 x n16 -> 8 x n8
            uint32_t bfr[8][2];
#pragma unroll
            for (int ni2 = 0; ni2 < 4; ni2++) {
                int row = wn * 64 + ni2 * 16 + lrow;
                uint32_t r0, r1, r2, r3;
                ldsm_x4(r0, r1, r2, r3, sB + swz128(row * 128 + kb));
                bfr[ni2 * 2][0] = r0;     bfr[ni2 * 2][1] = r2;
                bfr[ni2 * 2 + 1][0] = r1; bfr[ni2 * 2 + 1][1] = r3;
            }
#pragma unroll
            for (int mi = 0; mi < 2; mi++)
#pragma unroll
                for (int ni = 0; ni < 8; ni++)
                    mma16816(acc[mi][ni], a[mi][0], a[mi][1], a[mi][2], a[mi][3],
                             bfr[ni][0], bfr[ni][1]);
        }
        __syncthreads();
    }

    // ---- fused epilogue ----
    const float* sx2 = (const float*)(smem + OFF_X2S);
    const int qrow = lane >> 2;        // 0..7
    const int qcol = (lane & 3) * 2;   // 0,2,4,6

    float p2v[2][2];
#pragma unroll
    for (int mi = 0; mi < 2; mi++) {
        int r0 = mt * 128 + wm * 32 + mi * 16 + qrow;
        p2v[mi][0] = g_p2[r0];
        p2v[mi][1] = g_p2[r0 + 8];
    }

#pragma unroll
    for (int mi = 0; mi < 2; mi++) {
#pragma unroll
        for (int half = 0; half < 2; half++) {  // c0,c1 (row) / c2,c3 (row+8)
            int r = mt * 128 + wm * 32 + mi * 16 + qrow + half * 8;
            if (r >= 2000) continue;
            float p2r = p2v[mi][half];
#pragma unroll
            for (int ni = 0; ni < 8; ni++) {
                int nl = wn * 64 + ni * 8 + qcol;  // local col in tile
                float v0 = acc[mi][ni][half * 2];
                float v1 = acc[mi][ni][half * 2 + 1];
                float s0 = sx2[nl] + p2r;
                float s1 = sx2[nl + 1] + p2r;
                float d0 = fmaxf(fmaf(-2.f, v0, s0), 0.f);
                float d1 = fmaxf(fmaf(-2.f, v1, s1), 0.f);
                float u0 = __fdividef(1.f - EPSV, d0 + EPSV);
                float u1 = __fdividef(1.f - EPSV, d1 + EPSV);
                float a0 = (u0 > 0.03f)
                               ? logf(1.f + u0)
                               : u0 * fmaf(u0, fmaf(u0, 0.3333333433f, -0.5f), 1.f);
                float a1 = (u1 > 0.03f)
                               ? logf(1.f + u1)
                               : u1 * fmaf(u1, fmaf(u1, 0.3333333433f, -0.5f), 1.f);
                int n = nt * 128 + nl;
                int b = n / 196;
                int hw = n - b * 196;
                float* o = out + ((size_t)b * 2000 + r) * 196 + hw;
                if (hw < 195) {
                    float2 v = make_float2(a0, a1);
                    *reinterpret_cast<float2*>(o) = v;
                } else {
                    o[0] = a0;
                    out[((size_t)(b + 1) * 2000 + r) * 196] = a1;
                }
            }
        }
    }
}

// ---------------- launch ----------------
extern "C" void kernel_launch(void* const* d_in, const int* in_sizes, int n_in,
                              void* d_out, int out_size) {
    const float* x = (const float*)d_in[0];       // (64, 512, 14, 14)
    const float* protos = (const float*)d_in[1];  // (2000, 512, 1, 1)
    float* out = (float*)d_out;                   // (64, 2000, 14, 14)
    (void)in_sizes; (void)n_in; (void)out_size;

    cudaFuncSetAttribute(gemm_kernel, cudaFuncAttributeMaxDynamicSharedMemorySize, SMEM_SZ);

    prep_protos<<<dim3(MT_N, KC_N), 256>>>(protos);
    prep_p2<<<256, 256>>>(protos);
    prep_x<<<dim3(NT_N, KC_N), 128>>>(x);
    reduce_x2<<<NPIX / 256, 256>>>();
    gemm_kernel<<<dim3(NT_N, MT_N), 256, SMEM_SZ>>>(out);
}